// round 4
// baseline (speedup 1.0000x reference)
#include <cuda_runtime.h>
#include <cuda_bf16.h>

// ---------------------------------------------------------------------------
// SpectralMSA channel attention — Round 4: double-buffered bf16x3 GEMMs.
//   qkv = x @ Wqkv^T ; attn = softmax(k^T q / alpha) ; out = P @ v
//   y = out @ Wproj^T + bproj
// GEMM1/GEMM3: mma.sync m16n8k16 bf16, split-2 operands, 3 products, fp32 acc.
// Mainloop: 2-stage smem double buffer, ONE __syncthreads per k16 iteration.
// ---------------------------------------------------------------------------

namespace {
constexpr int kB = 4;
constexpr int kN = 4096;
constexpr int kC = 1024;
constexpr int kH = 16;
constexpr int kD = 64;
constexpr int kM = kB * kN;        // 16384
constexpr int kQKV = 3 * kC;       // 3072
constexpr int kSplits = 8;
}

__device__ float g_qkv[(size_t)kM * kQKV];
__device__ float g_attn[(size_t)kSplits * kB * kH * kD * kD];
__device__ float g_attnP[(size_t)kB * kH * kD * kD];
__device__ float g_out[(size_t)kM * kC];

__device__ __forceinline__ void mma_bf16(float& d0, float& d1, float& d2, float& d3,
                                         unsigned a0, unsigned a1, unsigned a2, unsigned a3,
                                         unsigned b0, unsigned b1)
{
    asm volatile(
        "mma.sync.aligned.m16n8k16.row.col.f32.bf16.bf16.f32 "
        "{%0,%1,%2,%3},{%4,%5,%6,%7},{%8,%9},{%0,%1,%2,%3};"
        : "+f"(d0), "+f"(d1), "+f"(d2), "+f"(d3)
        : "r"(a0), "r"(a1), "r"(a2), "r"(a3), "r"(b0), "r"(b1));
}

__device__ __forceinline__ void split4(float4 v, unsigned& h0, unsigned& h1,
                                       unsigned& l0, unsigned& l1)
{
    __nv_bfloat16 ax = __float2bfloat16_rn(v.x);
    __nv_bfloat16 ay = __float2bfloat16_rn(v.y);
    __nv_bfloat16 az = __float2bfloat16_rn(v.z);
    __nv_bfloat16 aw = __float2bfloat16_rn(v.w);
    __nv_bfloat16 rx = __float2bfloat16_rn(v.x - __bfloat162float(ax));
    __nv_bfloat16 ry = __float2bfloat16_rn(v.y - __bfloat162float(ay));
    __nv_bfloat16 rz = __float2bfloat16_rn(v.z - __bfloat162float(az));
    __nv_bfloat16 rw = __float2bfloat16_rn(v.w - __bfloat162float(aw));
    __nv_bfloat162 p;
    p = __nv_bfloat162(ax, ay); h0 = *(unsigned*)&p;
    p = __nv_bfloat162(az, aw); h1 = *(unsigned*)&p;
    p = __nv_bfloat162(rx, ry); l0 = *(unsigned*)&p;
    p = __nv_bfloat162(rz, rw); l1 = *(unsigned*)&p;
}

// ---------------------------------------------------------------------------
// bf16x3 GEMM (NT), 128x128x16 block, 256 thr, warp tile 64x32, 2-stage smem.
// ---------------------------------------------------------------------------
template <bool HAS_BIAS>
__global__ __launch_bounds__(256)
void bf16x3_gemm_nt(const float* __restrict__ A, const float* __restrict__ B,
                    float* __restrict__ C, const float* __restrict__ bias,
                    int M, int N, int K)
{
    __shared__ unsigned AsH[2][8][136], AsL[2][8][136];
    __shared__ unsigned BsH[2][8][136], BsL[2][8][136];

    const int t = threadIdx.x;
    const int warp = t >> 5, lane = t & 31;
    const int wm = (warp & 1) * 64;
    const int wn = (warp >> 1) * 32;
    const int r = lane >> 2, c = lane & 3;
    const int m0 = blockIdx.y * 128, n0 = blockIdx.x * 128;

    const int lrow = t & 127;
    const int lc0  = (t >> 7) * 4;
    const int kp0  = lc0 >> 1;

    const float* Ag = A + (size_t)(m0 + lrow) * K + lc0;
    const float* Bg = B + (size_t)(n0 + lrow) * K + lc0;

    float acc[4][4][4];
#pragma unroll
    for (int i = 0; i < 4; ++i)
#pragma unroll
        for (int j = 0; j < 4; ++j)
#pragma unroll
            for (int q = 0; q < 4; ++q) acc[i][j][q] = 0.f;

    float4 pa[2], pb[2];
#pragma unroll
    for (int i = 0; i < 2; ++i) {
        pa[i] = *(const float4*)(Ag + 8 * i);
        pb[i] = *(const float4*)(Bg + 8 * i);
    }

    for (int k0 = 0; k0 < K; k0 += 32) {
#pragma unroll
        for (int half = 0; half < 2; ++half) {
            const int buf = half;
            const int kk0 = k0 + 16 * half;

            // stage current tile (split bf16) into buffer `buf`
#pragma unroll
            for (int i = 0; i < 2; ++i) {
                unsigned h0, h1, l0, l1;
                split4(pa[i], h0, h1, l0, l1);
                AsH[buf][kp0 + 4 * i][lrow] = h0;  AsH[buf][kp0 + 4 * i + 1][lrow] = h1;
                AsL[buf][kp0 + 4 * i][lrow] = l0;  AsL[buf][kp0 + 4 * i + 1][lrow] = l1;
                split4(pb[i], h0, h1, l0, l1);
                BsH[buf][kp0 + 4 * i][lrow] = h0;  BsH[buf][kp0 + 4 * i + 1][lrow] = h1;
                BsL[buf][kp0 + 4 * i][lrow] = l0;  BsL[buf][kp0 + 4 * i + 1][lrow] = l1;
            }
            __syncthreads();

            // prefetch next k16 tile (consumed at next store, after next sync)
            if (kk0 + 16 < K) {
#pragma unroll
                for (int i = 0; i < 2; ++i) {
                    pa[i] = *(const float4*)(Ag + kk0 + 16 + 8 * i);
                    pb[i] = *(const float4*)(Bg + kk0 + 16 + 8 * i);
                }
            }

            // fragments + 48 mma from buffer `buf`
            unsigned aH[4][4], aL[4][4], bH[4][2], bL[4][2];
#pragma unroll
            for (int mt = 0; mt < 4; ++mt) {
                const int mr = wm + mt * 16 + r;
                aH[mt][0] = AsH[buf][c][mr];     aH[mt][1] = AsH[buf][c][mr + 8];
                aH[mt][2] = AsH[buf][c + 4][mr]; aH[mt][3] = AsH[buf][c + 4][mr + 8];
                aL[mt][0] = AsL[buf][c][mr];     aL[mt][1] = AsL[buf][c][mr + 8];
                aL[mt][2] = AsL[buf][c + 4][mr]; aL[mt][3] = AsL[buf][c + 4][mr + 8];
            }
#pragma unroll
            for (int nt = 0; nt < 4; ++nt) {
                const int nr = wn + nt * 8 + r;
                bH[nt][0] = BsH[buf][c][nr]; bH[nt][1] = BsH[buf][c + 4][nr];
                bL[nt][0] = BsL[buf][c][nr]; bL[nt][1] = BsL[buf][c + 4][nr];
            }
#pragma unroll
            for (int mt = 0; mt < 4; ++mt)
#pragma unroll
                for (int nt = 0; nt < 4; ++nt) {
                    mma_bf16(acc[mt][nt][0], acc[mt][nt][1], acc[mt][nt][2], acc[mt][nt][3],
                             aH[mt][0], aH[mt][1], aH[mt][2], aH[mt][3],
                             bL[nt][0], bL[nt][1]);
                    mma_bf16(acc[mt][nt][0], acc[mt][nt][1], acc[mt][nt][2], acc[mt][nt][3],
                             aL[mt][0], aL[mt][1], aL[mt][2], aL[mt][3],
                             bH[nt][0], bH[nt][1]);
                    mma_bf16(acc[mt][nt][0], acc[mt][nt][1], acc[mt][nt][2], acc[mt][nt][3],
                             aH[mt][0], aH[mt][1], aH[mt][2], aH[mt][3],
                             bH[nt][0], bH[nt][1]);
                }
            // NOTE: no trailing sync — next iteration's store targets the other
            // buffer; reads of that buffer finished before the previous sync.
        }
    }

#pragma unroll
    for (int mt = 0; mt < 4; ++mt) {
#pragma unroll
        for (int nt = 0; nt < 4; ++nt) {
            const int m = m0 + wm + mt * 16 + r;
            const int n = n0 + wn + nt * 8 + c * 2;
            float2 v0 = make_float2(acc[mt][nt][0], acc[mt][nt][1]);
            float2 v1 = make_float2(acc[mt][nt][2], acc[mt][nt][3]);
            if (HAS_BIAS) {
                const float b0v = bias[n], b1v = bias[n + 1];
                v0.x += b0v; v0.y += b1v;
                v1.x += b0v; v1.y += b1v;
            }
            *(float2*)(C + (size_t)m * N + n)       = v0;
            *(float2*)(C + (size_t)(m + 8) * N + n) = v1;
        }
    }
}

// ---------------------------------------------------------------------------
// Attention logits, split over N (deterministic partials). fp32 FMA.
// ---------------------------------------------------------------------------
__global__ __launch_bounds__(256)
void attn_logits_kernel()
{
    __shared__ float Ks[64][68];
    __shared__ float Qs[64][68];

    const int t = threadIdx.x;
    const int split = blockIdx.x;
    const int bh = blockIdx.y;
    const int b = bh >> 4, h = bh & 15;

    const float* base = g_qkv + (size_t)b * kN * kQKV + h * kD;
    const int td = t >> 4;
    const int te = t & 15;

    float acc[4][4];
#pragma unroll
    for (int i = 0; i < 4; ++i)
#pragma unroll
        for (int j = 0; j < 4; ++j) acc[i][j] = 0.f;

    const int nbeg = split * (kN / kSplits);
    for (int n0 = nbeg; n0 < nbeg + kN / kSplits; n0 += 64) {
#pragma unroll
        for (int i = 0; i < 4; ++i) {
            const int f = t + i * 256;
            const int row = f >> 4;
            const int c4 = (f & 15) * 4;
            const float* p = base + (size_t)(n0 + row) * kQKV + c4;
            *(float4*)&Qs[row][c4] = *(const float4*)(p);
            *(float4*)&Ks[row][c4] = *(const float4*)(p + kC);
        }
        __syncthreads();
#pragma unroll
        for (int nn = 0; nn < 64; ++nn) {
            float a[4], q[4];
            *(float4*)a = *(const float4*)&Ks[nn][td * 4];
            *(float4*)q = *(const float4*)&Qs[nn][te * 4];
#pragma unroll
            for (int i = 0; i < 4; ++i)
#pragma unroll
                for (int j = 0; j < 4; ++j)
                    acc[i][j] = fmaf(a[i], q[j], acc[i][j]);
        }
        __syncthreads();
    }

    float* o = g_attn + ((size_t)split * (kB * kH) + bh) * (kD * kD);
#pragma unroll
    for (int i = 0; i < 4; ++i)
#pragma unroll
        for (int j = 0; j < 4; ++j)
            o[(td * 4 + i) * kD + te * 4 + j] = acc[i][j];
}

// ---------------------------------------------------------------------------
__global__ void softmax_kernel(const float* __restrict__ alpha)
{
    const int row = blockIdx.x;
    const int t = threadIdx.x;
    const int h = (row >> 6) & 15;
    __shared__ float s[64];

    float v = 0.f;
#pragma unroll
    for (int sp = 0; sp < kSplits; ++sp)
        v += g_attn[(size_t)sp * (kB * kH * kD * kD) + (size_t)row * kD + t];
    v /= alpha[h];

    s[t] = v;
    __syncthreads();
    for (int off = 32; off > 0; off >>= 1) {
        if (t < off) s[t] = fmaxf(s[t], s[t + off]);
        __syncthreads();
    }
    const float mx = s[0];
    __syncthreads();
    const float e = expf(v - mx);
    s[t] = e;
    __syncthreads();
    for (int off = 32; off > 0; off >>= 1) {
        if (t < off) s[t] += s[t + off];
        __syncthreads();
    }
    g_attnP[(size_t)row * kD + t] = e / s[0];
}

// ---------------------------------------------------------------------------
__global__ __launch_bounds__(256)
void pv_kernel()
{
    __shared__ float PsT[64][68];
    __shared__ float Vs[64][68];

    const int t = threadIdx.x;
    const int nt = blockIdx.x;
    const int bh = blockIdx.y;
    const int b = bh >> 4, h = bh & 15;

    const float* Pg = g_attnP + (size_t)bh * (kD * kD);
#pragma unroll
    for (int i = 0; i < 4; ++i) {
        const int f = t + i * 256;
        const int dd = f >> 4;
        const int c4 = (f & 15) * 4;
        float4 v = *(const float4*)(Pg + dd * kD + c4);
        PsT[c4 + 0][dd] = v.x; PsT[c4 + 1][dd] = v.y;
        PsT[c4 + 2][dd] = v.z; PsT[c4 + 3][dd] = v.w;
    }
    const float* Vg = g_qkv + ((size_t)b * kN + nt * 64) * kQKV + 2 * kC + h * kD;
#pragma unroll
    for (int i = 0; i < 4; ++i) {
        const int f = t + i * 256;
        const int row = f >> 4;
        const int c4 = (f & 15) * 4;
        *(float4*)&Vs[row][c4] = *(const float4*)(Vg + (size_t)row * kQKV + c4);
    }
    __syncthreads();

    const int tn = t >> 3;
    const int tc = (t & 7) * 8;

    float acc[2][8];
#pragma unroll
    for (int i = 0; i < 2; ++i)
#pragma unroll
        for (int j = 0; j < 8; ++j) acc[i][j] = 0.f;

#pragma unroll
    for (int e = 0; e < 64; ++e) {
        float p[8];
        *(float4*)(p)     = *(const float4*)&PsT[e][tc];
        *(float4*)(p + 4) = *(const float4*)&PsT[e][tc + 4];
#pragma unroll
        for (int i = 0; i < 2; ++i) {
            const float v = Vs[tn * 2 + i][e];
#pragma unroll
            for (int j = 0; j < 8; ++j)
                acc[i][j] = fmaf(v, p[j], acc[i][j]);
        }
    }

#pragma unroll
    for (int i = 0; i < 2; ++i) {
        const size_t n = (size_t)b * kN + nt * 64 + tn * 2 + i;
        float* dst = g_out + n * kC + h * kD + tc;
        *(float4*)(dst)     = make_float4(acc[i][0], acc[i][1], acc[i][2], acc[i][3]);
        *(float4*)(dst + 4) = make_float4(acc[i][4], acc[i][5], acc[i][6], acc[i][7]);
    }
}

// ---------------------------------------------------------------------------
extern "C" void kernel_launch(void* const* d_in, const int* in_sizes, int n_in,
                              void* d_out, int out_size)
{
    const float* x = nullptr;
    const float* Wqkv = nullptr;
    const float* Wproj = nullptr;
    const float* bproj = nullptr;
    const float* alpha = nullptr;
    for (int i = 0; i < n_in; ++i) {
        switch (in_sizes[i]) {
            case kM * kC:    x     = (const float*)d_in[i]; break;
            case kQKV * kC:  Wqkv  = (const float*)d_in[i]; break;
            case kC * kC:    Wproj = (const float*)d_in[i]; break;
            case kC:         bproj = (const float*)d_in[i]; break;
            case kH:         alpha = (const float*)d_in[i]; break;
            default: break;
        }
    }

    float* qkv = nullptr;
    float* outp = nullptr;
    cudaGetSymbolAddress((void**)&qkv, g_qkv);
    cudaGetSymbolAddress((void**)&outp, g_out);

    dim3 g1(kQKV / 128, kM / 128);
    bf16x3_gemm_nt<false><<<g1, 256>>>(x, Wqkv, qkv, nullptr, kM, kQKV, kC);

    attn_logits_kernel<<<dim3(kSplits, kB * kH), 256>>>();

    softmax_kernel<<<kB * kH * kD, kD>>>(alpha);

    pv_kernel<<<dim3(kN / 64, kB * kH), 256>>>();

    dim3 g3(kC / 128, kM / 128);
    bf16x3_gemm_nt<true><<<g3, 256>>>(outp, Wproj, (float*)d_out, bproj, kM, kC, kC);
}

// round 6
// speedup vs baseline: 1.2351x; 1.2351x over previous
#include <cuda_runtime.h>
#include <cuda_bf16.h>

// ---------------------------------------------------------------------------
// SpectralMSA channel attention — Round 6: R3 bf16x3 mma.sync GEMMs +
// head-major qkv layout [3][B][H][N][64] written by GEMM1's epilogue, so the
// attention kernels (logits / pv) read fully contiguous rows (DRAM-bound
// instead of L1tex-wavefront bound).
// ---------------------------------------------------------------------------

namespace {
constexpr int kB = 4;
constexpr int kN = 4096;
constexpr int kC = 1024;
constexpr int kH = 16;
constexpr int kD = 64;
constexpr int kM = kB * kN;        // 16384
constexpr int kQKV = 3 * kC;       // 3072
constexpr int kSplits = 8;
}

// g_qkv layout: [sel(3)][b(4)][h(16)][n(4096)][d(64)]
__device__ float g_qkv[(size_t)3 * kB * kH * kN * kD];
__device__ float g_attn[(size_t)kSplits * kB * kH * kD * kD];
__device__ float g_attnP[(size_t)kB * kH * kD * kD];
__device__ float g_out[(size_t)kM * kC];

__device__ __forceinline__ void mma_bf16(float& d0, float& d1, float& d2, float& d3,
                                         unsigned a0, unsigned a1, unsigned a2, unsigned a3,
                                         unsigned b0, unsigned b1)
{
    asm volatile(
        "mma.sync.aligned.m16n8k16.row.col.f32.bf16.bf16.f32 "
        "{%0,%1,%2,%3},{%4,%5,%6,%7},{%8,%9},{%0,%1,%2,%3};"
        : "+f"(d0), "+f"(d1), "+f"(d2), "+f"(d3)
        : "r"(a0), "r"(a1), "r"(a2), "r"(a3), "r"(b0), "r"(b1));
}

__device__ __forceinline__ void split4(float4 v, unsigned& h0, unsigned& h1,
                                       unsigned& l0, unsigned& l1)
{
    __nv_bfloat16 ax = __float2bfloat16_rn(v.x);
    __nv_bfloat16 ay = __float2bfloat16_rn(v.y);
    __nv_bfloat16 az = __float2bfloat16_rn(v.z);
    __nv_bfloat16 aw = __float2bfloat16_rn(v.w);
    __nv_bfloat16 rx = __float2bfloat16_rn(v.x - __bfloat162float(ax));
    __nv_bfloat16 ry = __float2bfloat16_rn(v.y - __bfloat162float(ay));
    __nv_bfloat16 rz = __float2bfloat16_rn(v.z - __bfloat162float(az));
    __nv_bfloat16 rw = __float2bfloat16_rn(v.w - __bfloat162float(aw));
    __nv_bfloat162 p;
    p = __nv_bfloat162(ax, ay); h0 = *(unsigned*)&p;
    p = __nv_bfloat162(az, aw); h1 = *(unsigned*)&p;
    p = __nv_bfloat162(rx, ry); l0 = *(unsigned*)&p;
    p = __nv_bfloat162(rz, rw); l1 = *(unsigned*)&p;
}

// Epilogue write modes
enum { OUT_PLAIN = 0, OUT_PLAIN_BIAS = 1, OUT_QKV_HM = 2 };

__device__ __forceinline__ void write_qkv_hm(int m, int n, float2 v)
{
    const int sel = n >> 10;
    const int h   = (n >> 6) & 15;
    const int d   = n & 63;
    const int b   = m >> 12;
    const int ntk = m & 4095;
    float* dst = g_qkv +
        ((((size_t)sel * kB + b) * kH + h) * kN + ntk) * kD + d;
    *(float2*)dst = v;
}

// ---------------------------------------------------------------------------
// bf16x3 GEMM (NT): C[m,n] = sum_k A[m,k]*B[n,k]
// Block 128x128x16, 256 thr, warp tile 64x32 (R3 config — best known).
// ---------------------------------------------------------------------------
template <int OUT_MODE>
__global__ __launch_bounds__(256)
void bf16x3_gemm_nt(const float* __restrict__ A, const float* __restrict__ B,
                    float* __restrict__ C, const float* __restrict__ bias,
                    int M, int N, int K)
{
    __shared__ unsigned AsH[8][136], AsL[8][136];
    __shared__ unsigned BsH[8][136], BsL[8][136];

    const int t = threadIdx.x;
    const int warp = t >> 5, lane = t & 31;
    const int wm = (warp & 1) * 64;
    const int wn = (warp >> 1) * 32;
    const int r = lane >> 2, c = lane & 3;
    const int m0 = blockIdx.y * 128, n0 = blockIdx.x * 128;

    const int lrow = t & 127;
    const int lc0  = (t >> 7) * 4;
    const int kp0  = lc0 >> 1;

    const float* Ag = A + (size_t)(m0 + lrow) * K + lc0;
    const float* Bg = B + (size_t)(n0 + lrow) * K + lc0;

    float acc[4][4][4];
#pragma unroll
    for (int i = 0; i < 4; ++i)
#pragma unroll
        for (int j = 0; j < 4; ++j)
#pragma unroll
            for (int q = 0; q < 4; ++q) acc[i][j][q] = 0.f;

    float4 pa[2], pb[2];
#pragma unroll
    for (int i = 0; i < 2; ++i) {
        pa[i] = *(const float4*)(Ag + 8 * i);
        pb[i] = *(const float4*)(Bg + 8 * i);
    }

    for (int k0 = 0; k0 < K; k0 += 16) {
#pragma unroll
        for (int i = 0; i < 2; ++i) {
            unsigned h0, h1, l0, l1;
            split4(pa[i], h0, h1, l0, l1);
            AsH[kp0 + 4 * i][lrow] = h0;  AsH[kp0 + 4 * i + 1][lrow] = h1;
            AsL[kp0 + 4 * i][lrow] = l0;  AsL[kp0 + 4 * i + 1][lrow] = l1;
            split4(pb[i], h0, h1, l0, l1);
            BsH[kp0 + 4 * i][lrow] = h0;  BsH[kp0 + 4 * i + 1][lrow] = h1;
            BsL[kp0 + 4 * i][lrow] = l0;  BsL[kp0 + 4 * i + 1][lrow] = l1;
        }
        __syncthreads();

        if (k0 + 16 < K) {
#pragma unroll
            for (int i = 0; i < 2; ++i) {
                pa[i] = *(const float4*)(Ag + k0 + 16 + 8 * i);
                pb[i] = *(const float4*)(Bg + k0 + 16 + 8 * i);
            }
        }

        unsigned aH[4][4], aL[4][4], bH[4][2], bL[4][2];
#pragma unroll
        for (int mt = 0; mt < 4; ++mt) {
            const int mr = wm + mt * 16 + r;
            aH[mt][0] = AsH[c][mr];     aH[mt][1] = AsH[c][mr + 8];
            aH[mt][2] = AsH[c + 4][mr]; aH[mt][3] = AsH[c + 4][mr + 8];
            aL[mt][0] = AsL[c][mr];     aL[mt][1] = AsL[c][mr + 8];
            aL[mt][2] = AsL[c + 4][mr]; aL[mt][3] = AsL[c + 4][mr + 8];
        }
#pragma unroll
        for (int nt = 0; nt < 4; ++nt) {
            const int nr = wn + nt * 8 + r;
            bH[nt][0] = BsH[c][nr]; bH[nt][1] = BsH[c + 4][nr];
            bL[nt][0] = BsL[c][nr]; bL[nt][1] = BsL[c + 4][nr];
        }
#pragma unroll
        for (int mt = 0; mt < 4; ++mt)
#pragma unroll
            for (int nt = 0; nt < 4; ++nt) {
                mma_bf16(acc[mt][nt][0], acc[mt][nt][1], acc[mt][nt][2], acc[mt][nt][3],
                         aH[mt][0], aH[mt][1], aH[mt][2], aH[mt][3],
                         bL[nt][0], bL[nt][1]);
                mma_bf16(acc[mt][nt][0], acc[mt][nt][1], acc[mt][nt][2], acc[mt][nt][3],
                         aL[mt][0], aL[mt][1], aL[mt][2], aL[mt][3],
                         bH[nt][0], bH[nt][1]);
                mma_bf16(acc[mt][nt][0], acc[mt][nt][1], acc[mt][nt][2], acc[mt][nt][3],
                         aH[mt][0], aH[mt][1], aH[mt][2], aH[mt][3],
                         bH[nt][0], bH[nt][1]);
            }
        __syncthreads();
    }

#pragma unroll
    for (int mt = 0; mt < 4; ++mt) {
#pragma unroll
        for (int nt = 0; nt < 4; ++nt) {
            const int m = m0 + wm + mt * 16 + r;
            const int n = n0 + wn + nt * 8 + c * 2;
            float2 v0 = make_float2(acc[mt][nt][0], acc[mt][nt][1]);
            float2 v1 = make_float2(acc[mt][nt][2], acc[mt][nt][3]);
            if (OUT_MODE == OUT_QKV_HM) {
                write_qkv_hm(m, n, v0);
                write_qkv_hm(m + 8, n, v1);
            } else {
                if (OUT_MODE == OUT_PLAIN_BIAS) {
                    const float b0v = bias[n], b1v = bias[n + 1];
                    v0.x += b0v; v0.y += b1v;
                    v1.x += b0v; v1.y += b1v;
                }
                *(float2*)(C + (size_t)m * N + n)       = v0;
                *(float2*)(C + (size_t)(m + 8) * N + n) = v1;
            }
        }
    }
}

// ---------------------------------------------------------------------------
// Attention logits, split over N (deterministic partials). Head-major reads.
// ---------------------------------------------------------------------------
__global__ __launch_bounds__(256)
void attn_logits_kernel()
{
    __shared__ float Ks[64][68];
    __shared__ float Qs[64][68];

    const int t = threadIdx.x;
    const int split = blockIdx.x;
    const int bh = blockIdx.y;               // 0..63 = b*16+h

    const float* qbase = g_qkv + (size_t)(0 * kB * kH + bh) * kN * kD;
    const float* kbase = g_qkv + (size_t)(1 * kB * kH + bh) * kN * kD;
    const int td = t >> 4;
    const int te = t & 15;

    float acc[4][4];
#pragma unroll
    for (int i = 0; i < 4; ++i)
#pragma unroll
        for (int j = 0; j < 4; ++j) acc[i][j] = 0.f;

    const int nbeg = split * (kN / kSplits);
    for (int n0 = nbeg; n0 < nbeg + kN / kSplits; n0 += 64) {
#pragma unroll
        for (int i = 0; i < 4; ++i) {
            const int f = t + i * 256;
            const int row = f >> 4;
            const int c4 = (f & 15) * 4;
            const size_t off = (size_t)(n0 + row) * kD + c4;
            *(float4*)&Qs[row][c4] = *(const float4*)(qbase + off);
            *(float4*)&Ks[row][c4] = *(const float4*)(kbase + off);
        }
        __syncthreads();
#pragma unroll
        for (int nn = 0; nn < 64; ++nn) {
            float a[4], q[4];
            *(float4*)a = *(const float4*)&Ks[nn][td * 4];
            *(float4*)q = *(const float4*)&Qs[nn][te * 4];
#pragma unroll
            for (int i = 0; i < 4; ++i)
#pragma unroll
                for (int j = 0; j < 4; ++j)
                    acc[i][j] = fmaf(a[i], q[j], acc[i][j]);
        }
        __syncthreads();
    }

    float* o = g_attn + ((size_t)split * (kB * kH) + bh) * (kD * kD);
#pragma unroll
    for (int i = 0; i < 4; ++i)
#pragma unroll
        for (int j = 0; j < 4; ++j)
            o[(td * 4 + i) * kD + te * 4 + j] = acc[i][j];
}

// ---------------------------------------------------------------------------
__global__ void softmax_kernel(const float* __restrict__ alpha)
{
    const int row = blockIdx.x;
    const int t = threadIdx.x;
    const int h = (row >> 6) & 15;
    __shared__ float s[64];

    float v = 0.f;
#pragma unroll
    for (int sp = 0; sp < kSplits; ++sp)
        v += g_attn[(size_t)sp * (kB * kH * kD * kD) + (size_t)row * kD + t];
    v /= alpha[h];

    s[t] = v;
    __syncthreads();
    for (int off = 32; off > 0; off >>= 1) {
        if (t < off) s[t] = fmaxf(s[t], s[t + off]);
        __syncthreads();
    }
    const float mx = s[0];
    __syncthreads();
    const float e = expf(v - mx);
    s[t] = e;
    __syncthreads();
    for (int off = 32; off > 0; off >>= 1) {
        if (t < off) s[t] += s[t + off];
        __syncthreads();
    }
    g_attnP[(size_t)row * kD + t] = e / s[0];
}

// ---------------------------------------------------------------------------
// P @ V^T: out_tok[b,n,h*64+d] = sum_e P[b,h,d,e] * v[b,h,n,e]. Head-major V.
// ---------------------------------------------------------------------------
__global__ __launch_bounds__(256)
void pv_kernel()
{
    __shared__ float PsT[64][68];   // [e][d]
    __shared__ float Vs[64][68];    // [n_local][e]

    const int t = threadIdx.x;
    const int nt = blockIdx.x;
    const int bh = blockIdx.y;      // b*16+h
    const int b = bh >> 4, h = bh & 15;

    const float* Pg = g_attnP + (size_t)bh * (kD * kD);
#pragma unroll
    for (int i = 0; i < 4; ++i) {
        const int f = t + i * 256;
        const int dd = f >> 4;
        const int c4 = (f & 15) * 4;
        float4 v = *(const float4*)(Pg + dd * kD + c4);
        PsT[c4 + 0][dd] = v.x; PsT[c4 + 1][dd] = v.y;
        PsT[c4 + 2][dd] = v.z; PsT[c4 + 3][dd] = v.w;
    }
    const float* Vg = g_qkv + (size_t)(2 * kB * kH + bh) * kN * kD
                    + (size_t)nt * 64 * kD;
#pragma unroll
    for (int i = 0; i < 4; ++i) {
        const int f = t + i * 256;
        const int row = f >> 4;
        const int c4 = (f & 15) * 4;
        *(float4*)&Vs[row][c4] = *(const float4*)(Vg + (size_t)row * kD + c4);
    }
    __syncthreads();

    const int tn = t >> 3;
    const int tc = (t & 7) * 8;

    float acc[2][8];
#pragma unroll
    for (int i = 0; i < 2; ++i)
#pragma unroll
        for (int j = 0; j < 8; ++j) acc[i][j] = 0.f;

#pragma unroll
    for (int e = 0; e < 64; ++e) {
        float p[8];
        *(float4*)(p)     = *(const float4*)&PsT[e][tc];
        *(float4*)(p + 4) = *(const float4*)&PsT[e][tc + 4];
#pragma unroll
        for (int i = 0; i < 2; ++i) {
            const float v = Vs[tn * 2 + i][e];
#pragma unroll
            for (int j = 0; j < 8; ++j)
                acc[i][j] = fmaf(v, p[j], acc[i][j]);
        }
    }

#pragma unroll
    for (int i = 0; i < 2; ++i) {
        const size_t n = (size_t)b * kN + nt * 64 + tn * 2 + i;
        float* dst = g_out + n * kC + h * kD + tc;
        *(float4*)(dst)     = make_float4(acc[i][0], acc[i][1], acc[i][2], acc[i][3]);
        *(float4*)(dst + 4) = make_float4(acc[i][4], acc[i][5], acc[i][6], acc[i][7]);
    }
}

// ---------------------------------------------------------------------------
extern "C" void kernel_launch(void* const* d_in, const int* in_sizes, int n_in,
                              void* d_out, int out_size)
{
    const float* x = nullptr;
    const float* Wqkv = nullptr;
    const float* Wproj = nullptr;
    const float* bproj = nullptr;
    const float* alpha = nullptr;
    for (int i = 0; i < n_in; ++i) {
        switch (in_sizes[i]) {
            case kM * kC:    x     = (const float*)d_in[i]; break;
            case kQKV * kC:  Wqkv  = (const float*)d_in[i]; break;
            case kC * kC:    Wproj = (const float*)d_in[i]; break;
            case kC:         bproj = (const float*)d_in[i]; break;
            case kH:         alpha = (const float*)d_in[i]; break;
            default: break;
        }
    }

    float* outp = nullptr;
    cudaGetSymbolAddress((void**)&outp, g_out);

    // 1) QKV projection -> head-major qkv
    dim3 g1(kQKV / 128, kM / 128);
    bf16x3_gemm_nt<OUT_QKV_HM><<<g1, 256>>>(x, Wqkv, nullptr, nullptr,
                                            kM, kQKV, kC);

    // 2) Channel-attention logits (contiguous head-major reads)
    attn_logits_kernel<<<dim3(kSplits, kB * kH), 256>>>();

    // 3) Softmax
    softmax_kernel<<<kB * kH * kD, kD>>>(alpha);

    // 4) P @ V^T (contiguous head-major V reads)
    pv_kernel<<<dim3(kN / 64, kB * kH), 256>>>();

    // 5) Output projection + bias
    dim3 g3(kC / 128, kM / 128);
    bf16x3_gemm_nt<OUT_PLAIN_BIAS><<<g3, 256>>>(outp, Wproj, (float*)d_out,
                                                bproj, kM, kC, kC);
}

// round 7
// speedup vs baseline: 1.3435x; 1.0878x over previous
#include <cuda_runtime.h>
#include <cuda_bf16.h>

// ---------------------------------------------------------------------------
// SpectralMSA channel attention — Round 7: everything on mma.sync bf16x3.
//   GEMM1: qkv = x @ Wqkv^T -> head-major [3][B][H][N][64]
//   logits (mma): attn[d][e] = sum_n k[n][d] q[n][e]   (split-N partials)
//   softmax (fp32), pv (mma): out[n][d] = sum_e P[d][e] v[n][e]
//   GEMM3: y = out @ Wproj^T + bproj
// All matmuls: m16n8k16 bf16, split-2 operands (hi+lo), 3 products, fp32 acc.
// ---------------------------------------------------------------------------

namespace {
constexpr int kB = 4;
constexpr int kN = 4096;
constexpr int kC = 1024;
constexpr int kH = 16;
constexpr int kD = 64;
constexpr int kM = kB * kN;        // 16384
constexpr int kQKV = 3 * kC;       // 3072
constexpr int kSplits = 8;
}

// g_qkv layout: [sel(3)][b(4)][h(16)][n(4096)][d(64)]
__device__ float g_qkv[(size_t)3 * kB * kH * kN * kD];
__device__ float g_attn[(size_t)kSplits * kB * kH * kD * kD];
__device__ float g_attnP[(size_t)kB * kH * kD * kD];
__device__ float g_out[(size_t)kM * kC];

__device__ __forceinline__ void mma_bf16(float& d0, float& d1, float& d2, float& d3,
                                         unsigned a0, unsigned a1, unsigned a2, unsigned a3,
                                         unsigned b0, unsigned b1)
{
    asm volatile(
        "mma.sync.aligned.m16n8k16.row.col.f32.bf16.bf16.f32 "
        "{%0,%1,%2,%3},{%4,%5,%6,%7},{%8,%9},{%0,%1,%2,%3};"
        : "+f"(d0), "+f"(d1), "+f"(d2), "+f"(d3)
        : "r"(a0), "r"(a1), "r"(a2), "r"(a3), "r"(b0), "r"(b1));
}

// split two floats (consecutive k) -> packed bf16x2 hi word + lo word
__device__ __forceinline__ void split2pack(float a, float b, unsigned& h, unsigned& l)
{
    __nv_bfloat16 ha = __float2bfloat16_rn(a), hb = __float2bfloat16_rn(b);
    __nv_bfloat162 ph(ha, hb); h = *(unsigned*)&ph;
    __nv_bfloat162 pl(__float2bfloat16_rn(a - __bfloat162float(ha)),
                      __float2bfloat16_rn(b - __bfloat162float(hb)));
    l = *(unsigned*)&pl;
}

__device__ __forceinline__ void split4(float4 v, unsigned& h0, unsigned& h1,
                                       unsigned& l0, unsigned& l1)
{
    split2pack(v.x, v.y, h0, l0);
    split2pack(v.z, v.w, h1, l1);
}

// 3-product accumulate: HH + HL + LH
__device__ __forceinline__ void mma3(float* acc,
                                     const unsigned aH[4], const unsigned aL[4],
                                     const unsigned bH[2], const unsigned bL[2])
{
    mma_bf16(acc[0], acc[1], acc[2], acc[3], aH[0], aH[1], aH[2], aH[3], bL[0], bL[1]);
    mma_bf16(acc[0], acc[1], acc[2], acc[3], aL[0], aL[1], aL[2], aL[3], bH[0], bH[1]);
    mma_bf16(acc[0], acc[1], acc[2], acc[3], aH[0], aH[1], aH[2], aH[3], bH[0], bH[1]);
}

// Epilogue write modes
enum { OUT_PLAIN = 0, OUT_PLAIN_BIAS = 1, OUT_QKV_HM = 2 };

__device__ __forceinline__ void write_qkv_hm(int m, int n, float2 v)
{
    const int sel = n >> 10;
    const int h   = (n >> 6) & 15;
    const int d   = n & 63;
    const int b   = m >> 12;
    const int ntk = m & 4095;
    float* dst = g_qkv +
        ((((size_t)sel * kB + b) * kH + h) * kN + ntk) * kD + d;
    *(float2*)dst = v;
}

// ---------------------------------------------------------------------------
// bf16x3 GEMM (NT): C[m,n] = sum_k A[m,k]*B[n,k] — R3/R6 config (best known)
// ---------------------------------------------------------------------------
template <int OUT_MODE>
__global__ __launch_bounds__(256)
void bf16x3_gemm_nt(const float* __restrict__ A, const float* __restrict__ B,
                    float* __restrict__ C, const float* __restrict__ bias,
                    int M, int N, int K)
{
    __shared__ unsigned AsH[8][136], AsL[8][136];
    __shared__ unsigned BsH[8][136], BsL[8][136];

    const int t = threadIdx.x;
    const int warp = t >> 5, lane = t & 31;
    const int wm = (warp & 1) * 64;
    const int wn = (warp >> 1) * 32;
    const int r = lane >> 2, c = lane & 3;
    const int m0 = blockIdx.y * 128, n0 = blockIdx.x * 128;

    const int lrow = t & 127;
    const int lc0  = (t >> 7) * 4;
    const int kp0  = lc0 >> 1;

    const float* Ag = A + (size_t)(m0 + lrow) * K + lc0;
    const float* Bg = B + (size_t)(n0 + lrow) * K + lc0;

    float acc[4][4][4];
#pragma unroll
    for (int i = 0; i < 4; ++i)
#pragma unroll
        for (int j = 0; j < 4; ++j)
#pragma unroll
            for (int q = 0; q < 4; ++q) acc[i][j][q] = 0.f;

    float4 pa[2], pb[2];
#pragma unroll
    for (int i = 0; i < 2; ++i) {
        pa[i] = *(const float4*)(Ag + 8 * i);
        pb[i] = *(const float4*)(Bg + 8 * i);
    }

    for (int k0 = 0; k0 < K; k0 += 16) {
#pragma unroll
        for (int i = 0; i < 2; ++i) {
            unsigned h0, h1, l0, l1;
            split4(pa[i], h0, h1, l0, l1);
            AsH[kp0 + 4 * i][lrow] = h0;  AsH[kp0 + 4 * i + 1][lrow] = h1;
            AsL[kp0 + 4 * i][lrow] = l0;  AsL[kp0 + 4 * i + 1][lrow] = l1;
            split4(pb[i], h0, h1, l0, l1);
            BsH[kp0 + 4 * i][lrow] = h0;  BsH[kp0 + 4 * i + 1][lrow] = h1;
            BsL[kp0 + 4 * i][lrow] = l0;  BsL[kp0 + 4 * i + 1][lrow] = l1;
        }
        __syncthreads();

        if (k0 + 16 < K) {
#pragma unroll
            for (int i = 0; i < 2; ++i) {
                pa[i] = *(const float4*)(Ag + k0 + 16 + 8 * i);
                pb[i] = *(const float4*)(Bg + k0 + 16 + 8 * i);
            }
        }

        unsigned aH[4][4], aL[4][4], bH[4][2], bL[4][2];
#pragma unroll
        for (int mt = 0; mt < 4; ++mt) {
            const int mr = wm + mt * 16 + r;
            aH[mt][0] = AsH[c][mr];     aH[mt][1] = AsH[c][mr + 8];
            aH[mt][2] = AsH[c + 4][mr]; aH[mt][3] = AsH[c + 4][mr + 8];
            aL[mt][0] = AsL[c][mr];     aL[mt][1] = AsL[c][mr + 8];
            aL[mt][2] = AsL[c + 4][mr]; aL[mt][3] = AsL[c + 4][mr + 8];
        }
#pragma unroll
        for (int nt = 0; nt < 4; ++nt) {
            const int nr = wn + nt * 8 + r;
            bH[nt][0] = BsH[c][nr]; bH[nt][1] = BsH[c + 4][nr];
            bL[nt][0] = BsL[c][nr]; bL[nt][1] = BsL[c + 4][nr];
        }
#pragma unroll
        for (int mt = 0; mt < 4; ++mt)
#pragma unroll
            for (int nt = 0; nt < 4; ++nt)
                mma3(acc[mt][nt], aH[mt], aL[mt], bH[nt], bL[nt]);
        __syncthreads();
    }

#pragma unroll
    for (int mt = 0; mt < 4; ++mt) {
#pragma unroll
        for (int nt = 0; nt < 4; ++nt) {
            const int m = m0 + wm + mt * 16 + r;
            const int n = n0 + wn + nt * 8 + c * 2;
            float2 v0 = make_float2(acc[mt][nt][0], acc[mt][nt][1]);
            float2 v1 = make_float2(acc[mt][nt][2], acc[mt][nt][3]);
            if (OUT_MODE == OUT_QKV_HM) {
                write_qkv_hm(m, n, v0);
                write_qkv_hm(m + 8, n, v1);
            } else {
                if (OUT_MODE == OUT_PLAIN_BIAS) {
                    const float b0v = bias[n], b1v = bias[n + 1];
                    v0.x += b0v; v0.y += b1v;
                    v1.x += b0v; v1.y += b1v;
                }
                *(float2*)(C + (size_t)m * N + n)       = v0;
                *(float2*)(C + (size_t)(m + 8) * N + n) = v1;
            }
        }
    }
}

// ---------------------------------------------------------------------------
// Logits on tensor cores: partial[split][bh][d][e] = sum_{n in split} k.q
// A[m=d][k=n] = k^T, B[n=e][k=n] = q^T -> transpose-stage into [npair][d/e]
// planes. Block = 64x64 output, 8 warps (2m x 4n), warp tile 32x16.
// ---------------------------------------------------------------------------
__global__ __launch_bounds__(256)
void attn_logits_mma()
{
    __shared__ unsigned AH[32][72], AL[32][72];   // k^T planes
    __shared__ unsigned BH[32][72], BL[32][72];   // q^T planes

    const int t = threadIdx.x;
    const int warp = t >> 5, lane = t & 31;
    const int wm = (warp & 1) * 32;       // d
    const int wn = (warp >> 1) * 16;      // e
    const int r = lane >> 2, c = lane & 3;
    const int split = blockIdx.x, bh = blockIdx.y;

    const float* qb = g_qkv + (size_t)(0 * kB * kH + bh) * kN * kD;
    const float* kb = g_qkv + (size_t)(1 * kB * kH + bh) * kN * kD;

    float acc[2][2][4];
#pragma unroll
    for (int i = 0; i < 2; ++i)
#pragma unroll
        for (int j = 0; j < 2; ++j)
#pragma unroll
            for (int q = 0; q < 4; ++q) acc[i][j][q] = 0.f;

    const int nbeg = split * (kN / kSplits);
    for (int n0 = nbeg; n0 < nbeg + kN / kSplits; n0 += 64) {
        // transpose-stage: 512 tasks per matrix (32 token-pairs x 16 d-quads)
#pragma unroll
        for (int i = 0; i < 4; ++i) {
            const int f = t + i * 256;              // 0..1023
            const float* src = (f < 512) ? kb : qb;
            unsigned (*pH)[72] = (f < 512) ? AH : BH;
            unsigned (*pL)[72] = (f < 512) ? AL : BL;
            const int g  = f & 511;
            const int pr = g >> 4;                  // token pair 0..31
            const int d4 = (g & 15) * 4;
            const float* p0 = src + (size_t)(n0 + 2 * pr) * kD + d4;
            float4 v0 = *(const float4*)p0;
            float4 v1 = *(const float4*)(p0 + kD);
            split2pack(v0.x, v1.x, pH[pr][d4 + 0], pL[pr][d4 + 0]);
            split2pack(v0.y, v1.y, pH[pr][d4 + 1], pL[pr][d4 + 1]);
            split2pack(v0.z, v1.z, pH[pr][d4 + 2], pL[pr][d4 + 2]);
            split2pack(v0.w, v1.w, pH[pr][d4 + 3], pL[pr][d4 + 3]);
        }
        __syncthreads();

#pragma unroll
        for (int s = 0; s < 4; ++s) {
            const int base = 8 * s;
            unsigned aH[2][4], aL[2][4], bH[2][2], bL[2][2];
#pragma unroll
            for (int mt = 0; mt < 2; ++mt) {
                const int mr = wm + mt * 16 + r;
                aH[mt][0] = AH[base + c][mr];     aH[mt][1] = AH[base + c][mr + 8];
                aH[mt][2] = AH[base + c + 4][mr]; aH[mt][3] = AH[base + c + 4][mr + 8];
                aL[mt][0] = AL[base + c][mr];     aL[mt][1] = AL[base + c][mr + 8];
                aL[mt][2] = AL[base + c + 4][mr]; aL[mt][3] = AL[base + c + 4][mr + 8];
            }
#pragma unroll
            for (int nt = 0; nt < 2; ++nt) {
                const int nr = wn + nt * 8 + r;
                bH[nt][0] = BH[base + c][nr]; bH[nt][1] = BH[base + c + 4][nr];
                bL[nt][0] = BL[base + c][nr]; bL[nt][1] = BL[base + c + 4][nr];
            }
#pragma unroll
            for (int mt = 0; mt < 2; ++mt)
#pragma unroll
                for (int nt = 0; nt < 2; ++nt)
                    mma3(acc[mt][nt], aH[mt], aL[mt], bH[nt], bL[nt]);
        }
        __syncthreads();
    }

    float* o = g_attn + ((size_t)split * (kB * kH) + bh) * (kD * kD);
#pragma unroll
    for (int mt = 0; mt < 2; ++mt) {
#pragma unroll
        for (int nt = 0; nt < 2; ++nt) {
            const int dr = wm + mt * 16 + r;
            const int e0 = wn + nt * 8 + 2 * c;
            *(float2*)(o + dr * kD + e0)       = make_float2(acc[mt][nt][0], acc[mt][nt][1]);
            *(float2*)(o + (dr + 8) * kD + e0) = make_float2(acc[mt][nt][2], acc[mt][nt][3]);
        }
    }
}

// ---------------------------------------------------------------------------
__global__ void softmax_kernel(const float* __restrict__ alpha)
{
    const int row = blockIdx.x;
    const int t = threadIdx.x;
    const int h = (row >> 6) & 15;
    __shared__ float s[64];

    float v = 0.f;
#pragma unroll
    for (int sp = 0; sp < kSplits; ++sp)
        v += g_attn[(size_t)sp * (kB * kH * kD * kD) + (size_t)row * kD + t];
    v /= alpha[h];

    s[t] = v;
    __syncthreads();
    for (int off = 32; off > 0; off >>= 1) {
        if (t < off) s[t] = fmaxf(s[t], s[t + off]);
        __syncthreads();
    }
    const float mx = s[0];
    __syncthreads();
    const float e = expf(v - mx);
    s[t] = e;
    __syncthreads();
    for (int off = 32; off > 0; off >>= 1) {
        if (t < off) s[t] += s[t + off];
        __syncthreads();
    }
    g_attnP[(size_t)row * kD + t] = e / s[0];
}

// ---------------------------------------------------------------------------
// P @ V^T on tensor cores: out[n][d] = sum_e P[d][e] v[n][e]
// NT GEMM: A[m=n][k=e] = v (head-major, already k-major), B[n=d][k=e] = P.
// Block = 64 tokens x 64 d, 8 warps (2m x 4n), warp tile 32x16.
// ---------------------------------------------------------------------------
__global__ __launch_bounds__(256)
void pv_mma()
{
    __shared__ unsigned VH[32][72], VL[32][72];
    __shared__ unsigned PH[32][72], PL[32][72];

    const int t = threadIdx.x;
    const int warp = t >> 5, lane = t & 31;
    const int wm = (warp & 1) * 32;       // token
    const int wn = (warp >> 1) * 16;      // d
    const int r = lane >> 2, c = lane & 3;
    const int tk0 = blockIdx.x * 64;
    const int bh = blockIdx.y;
    const int b = bh >> 4, h = bh & 15;

    const float* Vg = g_qkv + (size_t)(2 * kB * kH + bh) * kN * kD
                    + (size_t)tk0 * kD;
    const float* Pg = g_attnP + (size_t)bh * (kD * kD);

    // stage V and P (both rows are k-major already)
#pragma unroll
    for (int i = 0; i < 4; ++i) {
        const int f = t + i * 256;
        const int row = f >> 4;
        const int e4 = (f & 15) * 4;
        const int kp = e4 >> 1;
        float4 v = *(const float4*)(Vg + (size_t)row * kD + e4);
        split2pack(v.x, v.y, VH[kp][row], VL[kp][row]);
        split2pack(v.z, v.w, VH[kp + 1][row], VL[kp + 1][row]);
        float4 p = *(const float4*)(Pg + row * kD + e4);
        split2pack(p.x, p.y, PH[kp][row], PL[kp][row]);
        split2pack(p.z, p.w, PH[kp + 1][row], PL[kp + 1][row]);
    }
    __syncthreads();

    float acc[2][2][4];
#pragma unroll
    for (int i = 0; i < 2; ++i)
#pragma unroll
        for (int j = 0; j < 2; ++j)
#pragma unroll
            for (int q = 0; q < 4; ++q) acc[i][j][q] = 0.f;

#pragma unroll
    for (int s = 0; s < 4; ++s) {
        const int base = 8 * s;
        unsigned aH[2][4], aL[2][4], bH[2][2], bL[2][2];
#pragma unroll
        for (int mt = 0; mt < 2; ++mt) {
            const int mr = wm + mt * 16 + r;
            aH[mt][0] = VH[base + c][mr];     aH[mt][1] = VH[base + c][mr + 8];
            aH[mt][2] = VH[base + c + 4][mr]; aH[mt][3] = VH[base + c + 4][mr + 8];
            aL[mt][0] = VL[base + c][mr];     aL[mt][1] = VL[base + c][mr + 8];
            aL[mt][2] = VL[base + c + 4][mr]; aL[mt][3] = VL[base + c + 4][mr + 8];
        }
#pragma unroll
        for (int nt = 0; nt < 2; ++nt) {
            const int nr = wn + nt * 8 + r;
            bH[nt][0] = PH[base + c][nr]; bH[nt][1] = PH[base + c + 4][nr];
            bL[nt][0] = PL[base + c][nr]; bL[nt][1] = PL[base + c + 4][nr];
        }
#pragma unroll
        for (int mt = 0; mt < 2; ++mt)
#pragma unroll
            for (int nt = 0; nt < 2; ++nt)
                mma3(acc[mt][nt], aH[mt], aL[mt], bH[nt], bL[nt]);
    }

#pragma unroll
    for (int mt = 0; mt < 2; ++mt) {
#pragma unroll
        for (int nt = 0; nt < 2; ++nt) {
            const int tok = tk0 + wm + mt * 16 + r;
            const int d0 = wn + nt * 8 + 2 * c;
            float* dst0 = g_out + ((size_t)b * kN + tok) * kC + h * kD + d0;
            float* dst1 = g_out + ((size_t)b * kN + tok + 8) * kC + h * kD + d0;
            *(float2*)dst0 = make_float2(acc[mt][nt][0], acc[mt][nt][1]);
            *(float2*)dst1 = make_float2(acc[mt][nt][2], acc[mt][nt][3]);
        }
    }
}

// ---------------------------------------------------------------------------
extern "C" void kernel_launch(void* const* d_in, const int* in_sizes, int n_in,
                              void* d_out, int out_size)
{
    const float* x = nullptr;
    const float* Wqkv = nullptr;
    const float* Wproj = nullptr;
    const float* bproj = nullptr;
    const float* alpha = nullptr;
    for (int i = 0; i < n_in; ++i) {
        switch (in_sizes[i]) {
            case kM * kC:    x     = (const float*)d_in[i]; break;
            case kQKV * kC:  Wqkv  = (const float*)d_in[i]; break;
            case kC * kC:    Wproj = (const float*)d_in[i]; break;
            case kC:         bproj = (const float*)d_in[i]; break;
            case kH:         alpha = (const float*)d_in[i]; break;
            default: break;
        }
    }

    float* outp = nullptr;
    cudaGetSymbolAddress((void**)&outp, g_out);

    // 1) QKV projection -> head-major qkv
    dim3 g1(kQKV / 128, kM / 128);
    bf16x3_gemm_nt<OUT_QKV_HM><<<g1, 256>>>(x, Wqkv, nullptr, nullptr,
                                            kM, kQKV, kC);

    // 2) Channel-attention logits on tensor cores
    attn_logits_mma<<<dim3(kSplits, kB * kH), 256>>>();

    // 3) Softmax
    softmax_kernel<<<kB * kH * kD, kD>>>(alpha);

    // 4) P @ V^T on tensor cores
    pv_mma<<<dim3(kN / 64, kB * kH), 256>>>();

    // 5) Output projection + bias
    dim3 g3(kC / 128, kM / 128);
    bf16x3_gemm_nt<OUT_PLAIN_BIAS><<<g3, 256>>>(outp, Wproj, (float*)d_out,
                                                bproj, kM, kC, kC);
}

// round 8
// speedup vs baseline: 1.3734x; 1.0223x over previous
#include <cuda_runtime.h>
#include <cuda_bf16.h>

// ---------------------------------------------------------------------------
// SpectralMSA channel attention — Round 8: pre-split bf16 operands.
//   split x/Wqkv/Wproj once -> gmem (hi, lo) bf16; pv epilogue emits split out.
//   GEMM mainloops: pure LDG(bf16)->STS->LDS->HMMA (no cvt chain, half bytes).
//   GEMM1 -> head-major qkv [3][B][H][N][64]; logits/pv on mma (R7 winners).
// ---------------------------------------------------------------------------

namespace {
constexpr int kB = 4;
constexpr int kN = 4096;
constexpr int kC = 1024;
constexpr int kH = 16;
constexpr int kD = 64;
constexpr int kM = kB * kN;        // 16384
constexpr int kQKV = 3 * kC;       // 3072
constexpr int kSplits = 8;
}

// fp32 scratch
__device__ float g_qkv[(size_t)3 * kB * kH * kN * kD];   // [sel][b][h][n][d]
__device__ float g_attn[(size_t)kSplits * kB * kH * kD * kD];
__device__ float g_attnP[(size_t)kB * kH * kD * kD];
// split-bf16 operands
__device__ __nv_bfloat16 g_xH[(size_t)kM * kC],      g_xL[(size_t)kM * kC];
__device__ __nv_bfloat16 g_wqkvH[(size_t)kQKV * kC], g_wqkvL[(size_t)kQKV * kC];
__device__ __nv_bfloat16 g_wprojH[(size_t)kC * kC],  g_wprojL[(size_t)kC * kC];
__device__ __nv_bfloat16 g_outH[(size_t)kM * kC],    g_outL[(size_t)kM * kC];

__device__ __forceinline__ void mma_bf16(float& d0, float& d1, float& d2, float& d3,
                                         unsigned a0, unsigned a1, unsigned a2, unsigned a3,
                                         unsigned b0, unsigned b1)
{
    asm volatile(
        "mma.sync.aligned.m16n8k16.row.col.f32.bf16.bf16.f32 "
        "{%0,%1,%2,%3},{%4,%5,%6,%7},{%8,%9},{%0,%1,%2,%3};"
        : "+f"(d0), "+f"(d1), "+f"(d2), "+f"(d3)
        : "r"(a0), "r"(a1), "r"(a2), "r"(a3), "r"(b0), "r"(b1));
}

__device__ __forceinline__ void split2pack(float a, float b, unsigned& h, unsigned& l)
{
    __nv_bfloat16 ha = __float2bfloat16_rn(a), hb = __float2bfloat16_rn(b);
    __nv_bfloat162 ph(ha, hb); h = *(unsigned*)&ph;
    __nv_bfloat162 pl(__float2bfloat16_rn(a - __bfloat162float(ha)),
                      __float2bfloat16_rn(b - __bfloat162float(hb)));
    l = *(unsigned*)&pl;
}

// 3-product accumulate: HL + LH + HH
__device__ __forceinline__ void mma3(float* acc,
                                     const unsigned aH[4], const unsigned aL[4],
                                     const unsigned bH[2], const unsigned bL[2])
{
    mma_bf16(acc[0], acc[1], acc[2], acc[3], aH[0], aH[1], aH[2], aH[3], bL[0], bL[1]);
    mma_bf16(acc[0], acc[1], acc[2], acc[3], aL[0], aL[1], aL[2], aL[3], bH[0], bH[1]);
    mma_bf16(acc[0], acc[1], acc[2], acc[3], aH[0], aH[1], aH[2], aH[3], bH[0], bH[1]);
}

// ---------------------------------------------------------------------------
// split fp32 -> (hi, lo) bf16, vectorized by 4
// ---------------------------------------------------------------------------
__global__ void split_kernel(const float* __restrict__ src,
                             __nv_bfloat16* __restrict__ hi,
                             __nv_bfloat16* __restrict__ lo, int n4)
{
    int i = blockIdx.x * blockDim.x + threadIdx.x;
    if (i >= n4) return;
    float4 v = ((const float4*)src)[i];
    unsigned h0, h1, l0, l1;
    split2pack(v.x, v.y, h0, l0);
    split2pack(v.z, v.w, h1, l1);
    ((uint2*)hi)[i] = make_uint2(h0, h1);
    ((uint2*)lo)[i] = make_uint2(l0, l1);
}

// Epilogue write modes
enum { OUT_PLAIN_BIAS = 1, OUT_QKV_HM = 2 };

__device__ __forceinline__ void write_qkv_hm(int m, int n, float2 v)
{
    const int sel = n >> 10;
    const int h   = (n >> 6) & 15;
    const int d   = n & 63;
    const int b   = m >> 12;
    const int ntk = m & 4095;
    float* dst = g_qkv +
        ((((size_t)sel * kB + b) * kH + h) * kN + ntk) * kD + d;
    *(float2*)dst = v;
}

// ---------------------------------------------------------------------------
// bf16x3 GEMM (NT) with pre-split inputs: C[m,n] = sum_k A[m,k]*B[n,k]
// Block 128x128x16, 256 thr, warp tile 64x32 (R3 config).
// ---------------------------------------------------------------------------
template <int OUT_MODE>
__global__ __launch_bounds__(256)
void bf16x3_gemm_nt(const __nv_bfloat16* __restrict__ AH,
                    const __nv_bfloat16* __restrict__ AL,
                    const __nv_bfloat16* __restrict__ BH,
                    const __nv_bfloat16* __restrict__ BL,
                    float* __restrict__ C, const float* __restrict__ bias,
                    int M, int N, int K)
{
    __shared__ unsigned AsH[8][136], AsL[8][136];
    __shared__ unsigned BsH[8][136], BsL[8][136];

    const int t = threadIdx.x;
    const int warp = t >> 5, lane = t & 31;
    const int wm = (warp & 1) * 64;
    const int wn = (warp >> 1) * 32;
    const int r = lane >> 2, c = lane & 3;
    const int m0 = blockIdx.y * 128, n0 = blockIdx.x * 128;

    const int lrow = t & 127;
    const int half = t >> 7;             // 0/1: bf16 cols half*8 .. half*8+7
    const int kp0  = half * 4;           // kpair base

    const __nv_bfloat16* AgH = AH + (size_t)(m0 + lrow) * K + half * 8;
    const __nv_bfloat16* AgL = AL + (size_t)(m0 + lrow) * K + half * 8;
    const __nv_bfloat16* BgH = BH + (size_t)(n0 + lrow) * K + half * 8;
    const __nv_bfloat16* BgL = BL + (size_t)(n0 + lrow) * K + half * 8;

    float acc[4][4][4];
#pragma unroll
    for (int i = 0; i < 4; ++i)
#pragma unroll
        for (int j = 0; j < 4; ++j)
#pragma unroll
            for (int q = 0; q < 4; ++q) acc[i][j][q] = 0.f;

    uint4 pah = *(const uint4*)AgH, pal = *(const uint4*)AgL;
    uint4 pbh = *(const uint4*)BgH, pbl = *(const uint4*)BgL;

    for (int k0 = 0; k0 < K; k0 += 16) {
        AsH[kp0 + 0][lrow] = pah.x; AsH[kp0 + 1][lrow] = pah.y;
        AsH[kp0 + 2][lrow] = pah.z; AsH[kp0 + 3][lrow] = pah.w;
        AsL[kp0 + 0][lrow] = pal.x; AsL[kp0 + 1][lrow] = pal.y;
        AsL[kp0 + 2][lrow] = pal.z; AsL[kp0 + 3][lrow] = pal.w;
        BsH[kp0 + 0][lrow] = pbh.x; BsH[kp0 + 1][lrow] = pbh.y;
        BsH[kp0 + 2][lrow] = pbh.z; BsH[kp0 + 3][lrow] = pbh.w;
        BsL[kp0 + 0][lrow] = pbl.x; BsL[kp0 + 1][lrow] = pbl.y;
        BsL[kp0 + 2][lrow] = pbl.z; BsL[kp0 + 3][lrow] = pbl.w;
        __syncthreads();

        if (k0 + 16 < K) {
            pah = *(const uint4*)(AgH + k0 + 16);
            pal = *(const uint4*)(AgL + k0 + 16);
            pbh = *(const uint4*)(BgH + k0 + 16);
            pbl = *(const uint4*)(BgL + k0 + 16);
        }

        unsigned aH[4][4], aL[4][4], bH[4][2], bL[4][2];
#pragma unroll
        for (int mt = 0; mt < 4; ++mt) {
            const int mr = wm + mt * 16 + r;
            aH[mt][0] = AsH[c][mr];     aH[mt][1] = AsH[c][mr + 8];
            aH[mt][2] = AsH[c + 4][mr]; aH[mt][3] = AsH[c + 4][mr + 8];
            aL[mt][0] = AsL[c][mr];     aL[mt][1] = AsL[c][mr + 8];
            aL[mt][2] = AsL[c + 4][mr]; aL[mt][3] = AsL[c + 4][mr + 8];
        }
#pragma unroll
        for (int nt = 0; nt < 4; ++nt) {
            const int nr = wn + nt * 8 + r;
            bH[nt][0] = BsH[c][nr]; bH[nt][1] = BsH[c + 4][nr];
            bL[nt][0] = BsL[c][nr]; bL[nt][1] = BsL[c + 4][nr];
        }
#pragma unroll
        for (int mt = 0; mt < 4; ++mt)
#pragma unroll
            for (int nt = 0; nt < 4; ++nt)
                mma3(acc[mt][nt], aH[mt], aL[mt], bH[nt], bL[nt]);
        __syncthreads();
    }

#pragma unroll
    for (int mt = 0; mt < 4; ++mt) {
#pragma unroll
        for (int nt = 0; nt < 4; ++nt) {
            const int m = m0 + wm + mt * 16 + r;
            const int n = n0 + wn + nt * 8 + c * 2;
            float2 v0 = make_float2(acc[mt][nt][0], acc[mt][nt][1]);
            float2 v1 = make_float2(acc[mt][nt][2], acc[mt][nt][3]);
            if (OUT_MODE == OUT_QKV_HM) {
                write_qkv_hm(m, n, v0);
                write_qkv_hm(m + 8, n, v1);
            } else {
                const float b0v = bias[n], b1v = bias[n + 1];
                v0.x += b0v; v0.y += b1v;
                v1.x += b0v; v1.y += b1v;
                *(float2*)(C + (size_t)m * N + n)       = v0;
                *(float2*)(C + (size_t)(m + 8) * N + n) = v1;
            }
        }
    }
}

// ---------------------------------------------------------------------------
// Logits on tensor cores (R7 winner): partial[split][bh] = K^T Q over split-N.
// ---------------------------------------------------------------------------
__global__ __launch_bounds__(256)
void attn_logits_mma()
{
    __shared__ unsigned AH[32][72], AL[32][72];   // k^T planes
    __shared__ unsigned BH[32][72], BL[32][72];   // q^T planes

    const int t = threadIdx.x;
    const int warp = t >> 5, lane = t & 31;
    const int wm = (warp & 1) * 32;
    const int wn = (warp >> 1) * 16;
    const int r = lane >> 2, c = lane & 3;
    const int split = blockIdx.x, bh = blockIdx.y;

    const float* qb = g_qkv + (size_t)(0 * kB * kH + bh) * kN * kD;
    const float* kb = g_qkv + (size_t)(1 * kB * kH + bh) * kN * kD;

    float acc[2][2][4];
#pragma unroll
    for (int i = 0; i < 2; ++i)
#pragma unroll
        for (int j = 0; j < 2; ++j)
#pragma unroll
            for (int q = 0; q < 4; ++q) acc[i][j][q] = 0.f;

    const int nbeg = split * (kN / kSplits);
    for (int n0 = nbeg; n0 < nbeg + kN / kSplits; n0 += 64) {
#pragma unroll
        for (int i = 0; i < 4; ++i) {
            const int f = t + i * 256;
            const float* src = (f < 512) ? kb : qb;
            unsigned (*pH)[72] = (f < 512) ? AH : BH;
            unsigned (*pL)[72] = (f < 512) ? AL : BL;
            const int g  = f & 511;
            const int pr = g >> 4;
            const int d4 = (g & 15) * 4;
            const float* p0 = src + (size_t)(n0 + 2 * pr) * kD + d4;
            float4 v0 = *(const float4*)p0;
            float4 v1 = *(const float4*)(p0 + kD);
            split2pack(v0.x, v1.x, pH[pr][d4 + 0], pL[pr][d4 + 0]);
            split2pack(v0.y, v1.y, pH[pr][d4 + 1], pL[pr][d4 + 1]);
            split2pack(v0.z, v1.z, pH[pr][d4 + 2], pL[pr][d4 + 2]);
            split2pack(v0.w, v1.w, pH[pr][d4 + 3], pL[pr][d4 + 3]);
        }
        __syncthreads();

#pragma unroll
        for (int s = 0; s < 4; ++s) {
            const int base = 8 * s;
            unsigned aH[2][4], aL[2][4], bH[2][2], bL[2][2];
#pragma unroll
            for (int mt = 0; mt < 2; ++mt) {
                const int mr = wm + mt * 16 + r;
                aH[mt][0] = AH[base + c][mr];     aH[mt][1] = AH[base + c][mr + 8];
                aH[mt][2] = AH[base + c + 4][mr]; aH[mt][3] = AH[base + c + 4][mr + 8];
                aL[mt][0] = AL[base + c][mr];     aL[mt][1] = AL[base + c][mr + 8];
                aL[mt][2] = AL[base + c + 4][mr]; aL[mt][3] = AL[base + c + 4][mr + 8];
            }
#pragma unroll
            for (int nt = 0; nt < 2; ++nt) {
                const int nr = wn + nt * 8 + r;
                bH[nt][0] = BH[base + c][nr]; bH[nt][1] = BH[base + c + 4][nr];
                bL[nt][0] = BL[base + c][nr]; bL[nt][1] = BL[base + c + 4][nr];
            }
#pragma unroll
            for (int mt = 0; mt < 2; ++mt)
#pragma unroll
                for (int nt = 0; nt < 2; ++nt)
                    mma3(acc[mt][nt], aH[mt], aL[mt], bH[nt], bL[nt]);
        }
        __syncthreads();
    }

    float* o = g_attn + ((size_t)split * (kB * kH) + bh) * (kD * kD);
#pragma unroll
    for (int mt = 0; mt < 2; ++mt) {
#pragma unroll
        for (int nt = 0; nt < 2; ++nt) {
            const int dr = wm + mt * 16 + r;
            const int e0 = wn + nt * 8 + 2 * c;
            *(float2*)(o + dr * kD + e0)       = make_float2(acc[mt][nt][0], acc[mt][nt][1]);
            *(float2*)(o + (dr + 8) * kD + e0) = make_float2(acc[mt][nt][2], acc[mt][nt][3]);
        }
    }
}

// ---------------------------------------------------------------------------
__global__ void softmax_kernel(const float* __restrict__ alpha)
{
    const int row = blockIdx.x;
    const int t = threadIdx.x;
    const int h = (row >> 6) & 15;
    __shared__ float s[64];

    float v = 0.f;
#pragma unroll
    for (int sp = 0; sp < kSplits; ++sp)
        v += g_attn[(size_t)sp * (kB * kH * kD * kD) + (size_t)row * kD + t];
    v /= alpha[h];

    s[t] = v;
    __syncthreads();
    for (int off = 32; off > 0; off >>= 1) {
        if (t < off) s[t] = fmaxf(s[t], s[t + off]);
        __syncthreads();
    }
    const float mx = s[0];
    __syncthreads();
    const float e = expf(v - mx);
    s[t] = e;
    __syncthreads();
    for (int off = 32; off > 0; off >>= 1) {
        if (t < off) s[t] += s[t + off];
        __syncthreads();
    }
    g_attnP[(size_t)row * kD + t] = e / s[0];
}

// ---------------------------------------------------------------------------
// P @ V^T on tensor cores (R7 winner) — epilogue writes SPLIT bf16 out.
// ---------------------------------------------------------------------------
__global__ __launch_bounds__(256)
void pv_mma()
{
    __shared__ unsigned VH[32][72], VL[32][72];
    __shared__ unsigned PH[32][72], PL[32][72];

    const int t = threadIdx.x;
    const int warp = t >> 5, lane = t & 31;
    const int wm = (warp & 1) * 32;       // token
    const int wn = (warp >> 1) * 16;      // d
    const int r = lane >> 2, c = lane & 3;
    const int tk0 = blockIdx.x * 64;
    const int bh = blockIdx.y;
    const int b = bh >> 4, h = bh & 15;

    const float* Vg = g_qkv + (size_t)(2 * kB * kH + bh) * kN * kD
                    + (size_t)tk0 * kD;
    const float* Pg = g_attnP + (size_t)bh * (kD * kD);

#pragma unroll
    for (int i = 0; i < 4; ++i) {
        const int f = t + i * 256;
        const int row = f >> 4;
        const int e4 = (f & 15) * 4;
        const int kp = e4 >> 1;
        float4 v = *(const float4*)(Vg + (size_t)row * kD + e4);
        split2pack(v.x, v.y, VH[kp][row], VL[kp][row]);
        split2pack(v.z, v.w, VH[kp + 1][row], VL[kp + 1][row]);
        float4 p = *(const float4*)(Pg + row * kD + e4);
        split2pack(p.x, p.y, PH[kp][row], PL[kp][row]);
        split2pack(p.z, p.w, PH[kp + 1][row], PL[kp + 1][row]);
    }
    __syncthreads();

    float acc[2][2][4];
#pragma unroll
    for (int i = 0; i < 2; ++i)
#pragma unroll
        for (int j = 0; j < 2; ++j)
#pragma unroll
            for (int q = 0; q < 4; ++q) acc[i][j][q] = 0.f;

#pragma unroll
    for (int s = 0; s < 4; ++s) {
        const int base = 8 * s;
        unsigned aH[2][4], aL[2][4], bH[2][2], bL[2][2];
#pragma unroll
        for (int mt = 0; mt < 2; ++mt) {
            const int mr = wm + mt * 16 + r;
            aH[mt][0] = VH[base + c][mr];     aH[mt][1] = VH[base + c][mr + 8];
            aH[mt][2] = VH[base + c + 4][mr]; aH[mt][3] = VH[base + c + 4][mr + 8];
            aL[mt][0] = VL[base + c][mr];     aL[mt][1] = VL[base + c][mr + 8];
            aL[mt][2] = VL[base + c + 4][mr]; aL[mt][3] = VL[base + c + 4][mr + 8];
        }
#pragma unroll
        for (int nt = 0; nt < 2; ++nt) {
            const int nr = wn + nt * 8 + r;
            bH[nt][0] = PH[base + c][nr]; bH[nt][1] = PH[base + c + 4][nr];
            bL[nt][0] = PL[base + c][nr]; bL[nt][1] = PL[base + c + 4][nr];
        }
#pragma unroll
        for (int mt = 0; mt < 2; ++mt)
#pragma unroll
            for (int nt = 0; nt < 2; ++nt)
                mma3(acc[mt][nt], aH[mt], aL[mt], bH[nt], bL[nt]);
    }

    // epilogue: split out[token][channel] directly into bf16 hi/lo arrays
#pragma unroll
    for (int mt = 0; mt < 2; ++mt) {
#pragma unroll
        for (int nt = 0; nt < 2; ++nt) {
            const int tok = tk0 + wm + mt * 16 + r;
            const int ch = h * kD + wn + nt * 8 + 2 * c;       // even
            const size_t i0 = (((size_t)b * kN + tok) * kC + ch) >> 1;
            const size_t i1 = (((size_t)b * kN + tok + 8) * kC + ch) >> 1;
            unsigned hw, lw;
            split2pack(acc[mt][nt][0], acc[mt][nt][1], hw, lw);
            ((unsigned*)g_outH)[i0] = hw;
            ((unsigned*)g_outL)[i0] = lw;
            split2pack(acc[mt][nt][2], acc[mt][nt][3], hw, lw);
            ((unsigned*)g_outH)[i1] = hw;
            ((unsigned*)g_outL)[i1] = lw;
        }
    }
}

// ---------------------------------------------------------------------------
extern "C" void kernel_launch(void* const* d_in, const int* in_sizes, int n_in,
                              void* d_out, int out_size)
{
    const float* x = nullptr;
    const float* Wqkv = nullptr;
    const float* Wproj = nullptr;
    const float* bproj = nullptr;
    const float* alpha = nullptr;
    for (int i = 0; i < n_in; ++i) {
        switch (in_sizes[i]) {
            case kM * kC:    x     = (const float*)d_in[i]; break;
            case kQKV * kC:  Wqkv  = (const float*)d_in[i]; break;
            case kC * kC:    Wproj = (const float*)d_in[i]; break;
            case kC:         bproj = (const float*)d_in[i]; break;
            case kH:         alpha = (const float*)d_in[i]; break;
            default: break;
        }
    }

    __nv_bfloat16 *xH, *xL, *wqH, *wqL, *wpH, *wpL, *oH, *oL;
    cudaGetSymbolAddress((void**)&xH, g_xH);     cudaGetSymbolAddress((void**)&xL, g_xL);
    cudaGetSymbolAddress((void**)&wqH, g_wqkvH); cudaGetSymbolAddress((void**)&wqL, g_wqkvL);
    cudaGetSymbolAddress((void**)&wpH, g_wprojH); cudaGetSymbolAddress((void**)&wpL, g_wprojL);
    cudaGetSymbolAddress((void**)&oH, g_outH);   cudaGetSymbolAddress((void**)&oL, g_outL);

    // 0) pre-split GEMM operands
    {
        int n4 = kM * kC / 4;
        split_kernel<<<(n4 + 255) / 256, 256>>>(x, xH, xL, n4);
        n4 = kQKV * kC / 4;
        split_kernel<<<(n4 + 255) / 256, 256>>>(Wqkv, wqH, wqL, n4);
        n4 = kC * kC / 4;
        split_kernel<<<(n4 + 255) / 256, 256>>>(Wproj, wpH, wpL, n4);
    }

    // 1) QKV projection -> head-major qkv
    dim3 g1(kQKV / 128, kM / 128);
    bf16x3_gemm_nt<OUT_QKV_HM><<<g1, 256>>>(xH, xL, wqH, wqL,
                                            nullptr, nullptr, kM, kQKV, kC);

    // 2) Channel-attention logits on tensor cores
    attn_logits_mma<<<dim3(kSplits, kB * kH), 256>>>();

    // 3) Softmax
    softmax_kernel<<<kB * kH * kD, kD>>>(alpha);

    // 4) P @ V^T on tensor cores (emits split bf16 out)
    pv_mma<<<dim3(kN / 64, kB * kH), 256>>>();

    // 5) Output projection + bias
    dim3 g3(kC / 128, kM / 128);
    bf16x3_gemm_nt<OUT_PLAIN_BIAS><<<g3, 256>>>(oH, oL, wpH, wpL,
                                                (float*)d_out, bproj, kM, kC, kC);
}

// round 9
// speedup vs baseline: 1.7906x; 1.3038x over previous
#include <cuda_runtime.h>
#include <cuda_bf16.h>
#include <cstdint>

// ---------------------------------------------------------------------------
// SpectralMSA channel attention — Round 9: cp.async + ldmatrix GEMM pipeline.
//   Pre-split bf16 operands (R8). GEMM mainloop: 2-stage cp.async double
//   buffer (k32/stage), [row][k] smem with 80B rows (conflict-free LDSM),
//   ldmatrix.x4 fragments, ONE __syncthreads per k32.
//   logits/pv on mma.sync (R7/R8 winners).
// ---------------------------------------------------------------------------

namespace {
constexpr int kB = 4;
constexpr int kN = 4096;
constexpr int kC = 1024;
constexpr int kH = 16;
constexpr int kD = 64;
constexpr int kM = kB * kN;        // 16384
constexpr int kQKV = 3 * kC;       // 3072
constexpr int kSplits = 8;
}

// fp32 scratch
__device__ float g_qkv[(size_t)3 * kB * kH * kN * kD];   // [sel][b][h][n][d]
__device__ float g_attn[(size_t)kSplits * kB * kH * kD * kD];
__device__ float g_attnP[(size_t)kB * kH * kD * kD];
// split-bf16 operands
__device__ __nv_bfloat16 g_xH[(size_t)kM * kC],      g_xL[(size_t)kM * kC];
__device__ __nv_bfloat16 g_wqkvH[(size_t)kQKV * kC], g_wqkvL[(size_t)kQKV * kC];
__device__ __nv_bfloat16 g_wprojH[(size_t)kC * kC],  g_wprojL[(size_t)kC * kC];
__device__ __nv_bfloat16 g_outH[(size_t)kM * kC],    g_outL[(size_t)kM * kC];

// ---------------- low-level helpers ----------------------------------------
__device__ __forceinline__ void mma_bf16(float& d0, float& d1, float& d2, float& d3,
                                         unsigned a0, unsigned a1, unsigned a2, unsigned a3,
                                         unsigned b0, unsigned b1)
{
    asm volatile(
        "mma.sync.aligned.m16n8k16.row.col.f32.bf16.bf16.f32 "
        "{%0,%1,%2,%3},{%4,%5,%6,%7},{%8,%9},{%0,%1,%2,%3};"
        : "+f"(d0), "+f"(d1), "+f"(d2), "+f"(d3)
        : "r"(a0), "r"(a1), "r"(a2), "r"(a3), "r"(b0), "r"(b1));
}

__device__ __forceinline__ void split2pack(float a, float b, unsigned& h, unsigned& l)
{
    __nv_bfloat16 ha = __float2bfloat16_rn(a), hb = __float2bfloat16_rn(b);
    __nv_bfloat162 ph(ha, hb); h = *(unsigned*)&ph;
    __nv_bfloat162 pl(__float2bfloat16_rn(a - __bfloat162float(ha)),
                      __float2bfloat16_rn(b - __bfloat162float(hb)));
    l = *(unsigned*)&pl;
}

// 3-product accumulate: HL + LH + HH
__device__ __forceinline__ void mma3(float* acc,
                                     const unsigned aH[4], const unsigned aL[4],
                                     unsigned bH0, unsigned bH1,
                                     unsigned bL0, unsigned bL1)
{
    mma_bf16(acc[0], acc[1], acc[2], acc[3], aH[0], aH[1], aH[2], aH[3], bL0, bL1);
    mma_bf16(acc[0], acc[1], acc[2], acc[3], aL[0], aL[1], aL[2], aL[3], bH0, bH1);
    mma_bf16(acc[0], acc[1], acc[2], acc[3], aH[0], aH[1], aH[2], aH[3], bH0, bH1);
}

__device__ __forceinline__ uint32_t smem_u32(const void* p) {
    uint32_t a;
    asm("{ .reg .u64 t; cvta.to.shared.u64 t, %1; cvt.u32.u64 %0, t; }"
        : "=r"(a) : "l"(p));
    return a;
}
__device__ __forceinline__ void cp16(uint32_t dst, const void* src) {
    asm volatile("cp.async.cg.shared.global [%0], [%1], 16;" :: "r"(dst), "l"(src));
}
__device__ __forceinline__ void cp_commit() {
    asm volatile("cp.async.commit_group;" ::: "memory");
}
template <int N>
__device__ __forceinline__ void cp_wait() {
    asm volatile("cp.async.wait_group %0;" :: "n"(N) : "memory");
}
__device__ __forceinline__ void ldsm4(unsigned* r, uint32_t addr) {
    asm volatile("ldmatrix.sync.aligned.m8n8.x4.shared.b16 {%0,%1,%2,%3}, [%4];"
                 : "=r"(r[0]), "=r"(r[1]), "=r"(r[2]), "=r"(r[3]) : "r"(addr));
}

// ---------------------------------------------------------------------------
// split fp32 -> (hi, lo) bf16, vectorized by 4
// ---------------------------------------------------------------------------
__global__ void split_kernel(const float* __restrict__ src,
                             __nv_bfloat16* __restrict__ hi,
                             __nv_bfloat16* __restrict__ lo, int n4)
{
    int i = blockIdx.x * blockDim.x + threadIdx.x;
    if (i >= n4) return;
    float4 v = ((const float4*)src)[i];
    unsigned h0, h1, l0, l1;
    split2pack(v.x, v.y, h0, l0);
    split2pack(v.z, v.w, h1, l1);
    ((uint2*)hi)[i] = make_uint2(h0, h1);
    ((uint2*)lo)[i] = make_uint2(l0, l1);
}

// Epilogue write modes
enum { OUT_PLAIN_BIAS = 1, OUT_QKV_HM = 2 };

__device__ __forceinline__ void write_qkv_hm(int m, int n, float2 v)
{
    const int sel = n >> 10;
    const int h   = (n >> 6) & 15;
    const int d   = n & 63;
    const int b   = m >> 12;
    const int ntk = m & 4095;
    float* dst = g_qkv +
        ((((size_t)sel * kB + b) * kH + h) * kN + ntk) * kD + d;
    *(float2*)dst = v;
}

// ---------------------------------------------------------------------------
// bf16x3 GEMM (NT), cp.async + ldmatrix pipeline.
// Block 128x128, K-stage 32, 2 stages, 256 thr, warp tile 64x32.
// smem per stage: 4 planes (AH, AL, BH, BL), each 128 rows x 80B.
// ---------------------------------------------------------------------------
namespace {
constexpr int ROWB  = 80;              // 32 bf16 (64B) + 16B pad: LDSM conflict-free
constexpr int PLANE = 128 * ROWB;      // 10240 B
constexpr int STAGE = 4 * PLANE;       // 40960 B
constexpr int SMEM_GEMM = 2 * STAGE;   // 81920 B
}

template <int OUT_MODE>
__global__ __launch_bounds__(256)
void bf16x3_gemm_cp(const __nv_bfloat16* __restrict__ AH,
                    const __nv_bfloat16* __restrict__ AL,
                    const __nv_bfloat16* __restrict__ BH,
                    const __nv_bfloat16* __restrict__ BL,
                    float* __restrict__ C, const float* __restrict__ bias,
                    int M, int N, int K)
{
    extern __shared__ char sm[];
    const uint32_t sbase = smem_u32(sm);

    const int t = threadIdx.x;
    const int warp = t >> 5, lane = t & 31;
    const int wm = (warp & 1) * 64;
    const int wn = (warp >> 1) * 32;
    const int m0 = blockIdx.y * 128, n0 = blockIdx.x * 128;

    // loader mapping: f = t + 256*j -> row = f>>2 (0..127), chunk = f&3
    const int lr0 = t >> 2, lc0 = t & 3;

    const __nv_bfloat16* pAH = AH + (size_t)m0 * K;
    const __nv_bfloat16* pAL = AL + (size_t)m0 * K;
    const __nv_bfloat16* pBH = BH + (size_t)n0 * K;
    const __nv_bfloat16* pBL = BL + (size_t)n0 * K;

    auto load_stage = [&](int st, int k0) {
        const uint32_t sb = sbase + st * STAGE;
#pragma unroll
        for (int j = 0; j < 2; ++j) {
            const int row = lr0 + j * 64;
            const int kc  = lc0;
            const uint32_t d = sb + row * ROWB + kc * 16;
            const size_t go = (size_t)row * K + k0 + kc * 8;
            cp16(d,             pAH + go);
            cp16(d + PLANE,     pAL + go);
            cp16(d + 2 * PLANE, pBH + go);
            cp16(d + 3 * PLANE, pBL + go);
        }
    };

    float acc[4][4][4];
#pragma unroll
    for (int i = 0; i < 4; ++i)
#pragma unroll
        for (int j = 0; j < 4; ++j)
#pragma unroll
            for (int q = 0; q < 4; ++q) acc[i][j][q] = 0.f;

    // LDSM lane geometry (same for A and B)
    const int quad = lane >> 3;          // 0..3
    const int l8   = lane & 7;
    const int roff = (quad & 1) * 8 + l8;    // row within 16-row tile
    const int koffB = (quad >> 1) * 16;      // 0 or 16 bytes (k 8-element halves)

    const int nch = K / 32;
    load_stage(0, 0);
    cp_commit();

    for (int ch = 0; ch < nch; ++ch) {
        cp_wait<0>();
        __syncthreads();

        if (ch + 1 < nch) {
            load_stage((ch + 1) & 1, (ch + 1) * 32);
            cp_commit();
        }

        const uint32_t sb = sbase + (ch & 1) * STAGE;
#pragma unroll
        for (int s = 0; s < 2; ++s) {
            const uint32_t kb = s * 32 + koffB;   // byte offset along k

            unsigned aH[4][4], aL[4][4];
#pragma unroll
            for (int mt = 0; mt < 4; ++mt) {
                const uint32_t ra = sb + (wm + mt * 16 + roff) * ROWB + kb;
                ldsm4(aH[mt], ra);
                ldsm4(aL[mt], ra + PLANE);
            }
            unsigned bfH[2][4], bfL[2][4];
#pragma unroll
            for (int pt = 0; pt < 2; ++pt) {
                const uint32_t rb = sb + 2 * PLANE
                                  + (wn + pt * 16 + roff) * ROWB + kb;
                ldsm4(bfH[pt], rb);
                ldsm4(bfL[pt], rb + PLANE);
            }
#pragma unroll
            for (int mt = 0; mt < 4; ++mt)
#pragma unroll
                for (int nt = 0; nt < 4; ++nt) {
                    const int pt = nt >> 1, hi = nt & 1;
                    mma3(acc[mt][nt], aH[mt], aL[mt],
                         bfH[pt][hi], bfH[pt][2 + hi],
                         bfL[pt][hi], bfL[pt][2 + hi]);
                }
        }
    }

    const int r = lane >> 2, c = lane & 3;
#pragma unroll
    for (int mt = 0; mt < 4; ++mt) {
#pragma unroll
        for (int nt = 0; nt < 4; ++nt) {
            const int m = m0 + wm + mt * 16 + r;
            const int n = n0 + wn + nt * 8 + c * 2;
            float2 v0 = make_float2(acc[mt][nt][0], acc[mt][nt][1]);
            float2 v1 = make_float2(acc[mt][nt][2], acc[mt][nt][3]);
            if (OUT_MODE == OUT_QKV_HM) {
                write_qkv_hm(m, n, v0);
                write_qkv_hm(m + 8, n, v1);
            } else {
                const float b0v = bias[n], b1v = bias[n + 1];
                v0.x += b0v; v0.y += b1v;
                v1.x += b0v; v1.y += b1v;
                *(float2*)(C + (size_t)m * N + n)       = v0;
                *(float2*)(C + (size_t)(m + 8) * N + n) = v1;
            }
        }
    }
}

// ---------------------------------------------------------------------------
// Logits on tensor cores (R7 winner): partial[split][bh] = K^T Q over split-N.
// ---------------------------------------------------------------------------
__global__ __launch_bounds__(256)
void attn_logits_mma()
{
    __shared__ unsigned AH[32][72], AL[32][72];   // k^T planes
    __shared__ unsigned BH[32][72], BL[32][72];   // q^T planes

    const int t = threadIdx.x;
    const int warp = t >> 5, lane = t & 31;
    const int wm = (warp & 1) * 32;
    const int wn = (warp >> 1) * 16;
    const int r = lane >> 2, c = lane & 3;
    const int split = blockIdx.x, bh = blockIdx.y;

    const float* qb = g_qkv + (size_t)(0 * kB * kH + bh) * kN * kD;
    const float* kb = g_qkv + (size_t)(1 * kB * kH + bh) * kN * kD;

    float acc[2][2][4];
#pragma unroll
    for (int i = 0; i < 2; ++i)
#pragma unroll
        for (int j = 0; j < 2; ++j)
#pragma unroll
            for (int q = 0; q < 4; ++q) acc[i][j][q] = 0.f;

    const int nbeg = split * (kN / kSplits);
    for (int n0 = nbeg; n0 < nbeg + kN / kSplits; n0 += 64) {
#pragma unroll
        for (int i = 0; i < 4; ++i) {
            const int f = t + i * 256;
            const float* src = (f < 512) ? kb : qb;
            unsigned (*pH)[72] = (f < 512) ? AH : BH;
            unsigned (*pL)[72] = (f < 512) ? AL : BL;
            const int g  = f & 511;
            const int pr = g >> 4;
            const int d4 = (g & 15) * 4;
            const float* p0 = src + (size_t)(n0 + 2 * pr) * kD + d4;
            float4 v0 = *(const float4*)p0;
            float4 v1 = *(const float4*)(p0 + kD);
            split2pack(v0.x, v1.x, pH[pr][d4 + 0], pL[pr][d4 + 0]);
            split2pack(v0.y, v1.y, pH[pr][d4 + 1], pL[pr][d4 + 1]);
            split2pack(v0.z, v1.z, pH[pr][d4 + 2], pL[pr][d4 + 2]);
            split2pack(v0.w, v1.w, pH[pr][d4 + 3], pL[pr][d4 + 3]);
        }
        __syncthreads();

#pragma unroll
        for (int s = 0; s < 4; ++s) {
            const int base = 8 * s;
            unsigned aH[2][4], aL[2][4], bH[2][2], bL[2][2];
#pragma unroll
            for (int mt = 0; mt < 2; ++mt) {
                const int mr = wm + mt * 16 + r;
                aH[mt][0] = AH[base + c][mr];     aH[mt][1] = AH[base + c][mr + 8];
                aH[mt][2] = AH[base + c + 4][mr]; aH[mt][3] = AH[base + c + 4][mr + 8];
                aL[mt][0] = AL[base + c][mr];     aL[mt][1] = AL[base + c][mr + 8];
                aL[mt][2] = AL[base + c + 4][mr]; aL[mt][3] = AL[base + c + 4][mr + 8];
            }
#pragma unroll
            for (int nt = 0; nt < 2; ++nt) {
                const int nr = wn + nt * 8 + r;
                bH[nt][0] = BH[base + c][nr]; bH[nt][1] = BH[base + c + 4][nr];
                bL[nt][0] = BL[base + c][nr]; bL[nt][1] = BL[base + c + 4][nr];
            }
#pragma unroll
            for (int mt = 0; mt < 2; ++mt)
#pragma unroll
                for (int nt = 0; nt < 2; ++nt)
                    mma3(acc[mt][nt], aH[mt], aL[mt],
                         bH[nt][0], bH[nt][1], bL[nt][0], bL[nt][1]);
        }
        __syncthreads();
    }

    float* o = g_attn + ((size_t)split * (kB * kH) + bh) * (kD * kD);
#pragma unroll
    for (int mt = 0; mt < 2; ++mt) {
#pragma unroll
        for (int nt = 0; nt < 2; ++nt) {
            const int dr = wm + mt * 16 + r;
            const int e0 = wn + nt * 8 + 2 * c;
            *(float2*)(o + dr * kD + e0)       = make_float2(acc[mt][nt][0], acc[mt][nt][1]);
            *(float2*)(o + (dr + 8) * kD + e0) = make_float2(acc[mt][nt][2], acc[mt][nt][3]);
        }
    }
}

// ---------------------------------------------------------------------------
__global__ void softmax_kernel(const float* __restrict__ alpha)
{
    const int row = blockIdx.x;
    const int t = threadIdx.x;
    const int h = (row >> 6) & 15;
    __shared__ float s[64];

    float v = 0.f;
#pragma unroll
    for (int sp = 0; sp < kSplits; ++sp)
        v += g_attn[(size_t)sp * (kB * kH * kD * kD) + (size_t)row * kD + t];
    v /= alpha[h];

    s[t] = v;
    __syncthreads();
    for (int off = 32; off > 0; off >>= 1) {
        if (t < off) s[t] = fmaxf(s[t], s[t + off]);
        __syncthreads();
    }
    const float mx = s[0];
    __syncthreads();
    const float e = expf(v - mx);
    s[t] = e;
    __syncthreads();
    for (int off = 32; off > 0; off >>= 1) {
        if (t < off) s[t] += s[t + off];
        __syncthreads();
    }
    g_attnP[(size_t)row * kD + t] = e / s[0];
}

// ---------------------------------------------------------------------------
// P @ V^T on tensor cores (R8 winner) — epilogue writes SPLIT bf16 out.
// ---------------------------------------------------------------------------
__global__ __launch_bounds__(256)
void pv_mma()
{
    __shared__ unsigned VH[32][72], VL[32][72];
    __shared__ unsigned PH[32][72], PL[32][72];

    const int t = threadIdx.x;
    const int warp = t >> 5, lane = t & 31;
    const int wm = (warp & 1) * 32;       // token
    const int wn = (warp >> 1) * 16;      // d
    const int r = lane >> 2, c = lane & 3;
    const int tk0 = blockIdx.x * 64;
    const int bh = blockIdx.y;
    const int b = bh >> 4, h = bh & 15;

    const float* Vg = g_qkv + (size_t)(2 * kB * kH + bh) * kN * kD
                    + (size_t)tk0 * kD;
    const float* Pg = g_attnP + (size_t)bh * (kD * kD);

#pragma unroll
    for (int i = 0; i < 4; ++i) {
        const int f = t + i * 256;
        const int row = f >> 4;
        const int e4 = (f & 15) * 4;
        const int kp = e4 >> 1;
        float4 v = *(const float4*)(Vg + (size_t)row * kD + e4);
        split2pack(v.x, v.y, VH[kp][row], VL[kp][row]);
        split2pack(v.z, v.w, VH[kp + 1][row], VL[kp + 1][row]);
        float4 p = *(const float4*)(Pg + row * kD + e4);
        split2pack(p.x, p.y, PH[kp][row], PL[kp][row]);
        split2pack(p.z, p.w, PH[kp + 1][row], PL[kp + 1][row]);
    }
    __syncthreads();

    float acc[2][2][4];
#pragma unroll
    for (int i = 0; i < 2; ++i)
#pragma unroll
        for (int j = 0; j < 2; ++j)
#pragma unroll
            for (int q = 0; q < 4; ++q) acc[i][j][q] = 0.f;

#pragma unroll
    for (int s = 0; s < 4; ++s) {
        const int base = 8 * s;
        unsigned aH[2][4], aL[2][4], bH[2][2], bL[2][2];
#pragma unroll
        for (int mt = 0; mt < 2; ++mt) {
            const int mr = wm + mt * 16 + r;
            aH[mt][0] = VH[base + c][mr];     aH[mt][1] = VH[base + c][mr + 8];
            aH[mt][2] = VH[base + c + 4][mr]; aH[mt][3] = VH[base + c + 4][mr + 8];
            aL[mt][0] = VL[base + c][mr];     aL[mt][1] = VL[base + c][mr + 8];
            aL[mt][2] = VL[base + c + 4][mr]; aL[mt][3] = VL[base + c + 4][mr + 8];
        }
#pragma unroll
        for (int nt = 0; nt < 2; ++nt) {
            const int nr = wn + nt * 8 + r;
            bH[nt][0] = PH[base + c][nr]; bH[nt][1] = PH[base + c + 4][nr];
            bL[nt][0] = PL[base + c][nr]; bL[nt][1] = PL[base + c + 4][nr];
        }
#pragma unroll
        for (int mt = 0; mt < 2; ++mt)
#pragma unroll
            for (int nt = 0; nt < 2; ++nt)
                mma3(acc[mt][nt], aH[mt], aL[mt],
                     bH[nt][0], bH[nt][1], bL[nt][0], bL[nt][1]);
    }

    // epilogue: split out[token][channel] directly into bf16 hi/lo arrays
#pragma unroll
    for (int mt = 0; mt < 2; ++mt) {
#pragma unroll
        for (int nt = 0; nt < 2; ++nt) {
            const int tok = tk0 + wm + mt * 16 + r;
            const int ch = h * kD + wn + nt * 8 + 2 * c;       // even
            const size_t i0 = (((size_t)b * kN + tok) * kC + ch) >> 1;
            const size_t i1 = (((size_t)b * kN + tok + 8) * kC + ch) >> 1;
            unsigned hw, lw;
            split2pack(acc[mt][nt][0], acc[mt][nt][1], hw, lw);
            ((unsigned*)g_outH)[i0] = hw;
            ((unsigned*)g_outL)[i0] = lw;
            split2pack(acc[mt][nt][2], acc[mt][nt][3], hw, lw);
            ((unsigned*)g_outH)[i1] = hw;
            ((unsigned*)g_outL)[i1] = lw;
        }
    }
}

// ---------------------------------------------------------------------------
extern "C" void kernel_launch(void* const* d_in, const int* in_sizes, int n_in,
                              void* d_out, int out_size)
{
    const float* x = nullptr;
    const float* Wqkv = nullptr;
    const float* Wproj = nullptr;
    const float* bproj = nullptr;
    const float* alpha = nullptr;
    for (int i = 0; i < n_in; ++i) {
        switch (in_sizes[i]) {
            case kM * kC:    x     = (const float*)d_in[i]; break;
            case kQKV * kC:  Wqkv  = (const float*)d_in[i]; break;
            case kC * kC:    Wproj = (const float*)d_in[i]; break;
            case kC:         bproj = (const float*)d_in[i]; break;
            case kH:         alpha = (const float*)d_in[i]; break;
            default: break;
        }
    }

    __nv_bfloat16 *xH, *xL, *wqH, *wqL, *wpH, *wpL, *oH, *oL;
    cudaGetSymbolAddress((void**)&xH, g_xH);     cudaGetSymbolAddress((void**)&xL, g_xL);
    cudaGetSymbolAddress((void**)&wqH, g_wqkvH); cudaGetSymbolAddress((void**)&wqL, g_wqkvL);
    cudaGetSymbolAddress((void**)&wpH, g_wprojH); cudaGetSymbolAddress((void**)&wpL, g_wprojL);
    cudaGetSymbolAddress((void**)&oH, g_outH);   cudaGetSymbolAddress((void**)&oL, g_outL);

    cudaFuncSetAttribute(bf16x3_gemm_cp<OUT_QKV_HM>,
                         cudaFuncAttributeMaxDynamicSharedMemorySize, SMEM_GEMM);
    cudaFuncSetAttribute(bf16x3_gemm_cp<OUT_PLAIN_BIAS>,
                         cudaFuncAttributeMaxDynamicSharedMemorySize, SMEM_GEMM);

    // 0) pre-split GEMM operands
    {
        int n4 = kM * kC / 4;
        split_kernel<<<(n4 + 255) / 256, 256>>>(x, xH, xL, n4);
        n4 = kQKV * kC / 4;
        split_kernel<<<(n4 + 255) / 256, 256>>>(Wqkv, wqH, wqL, n4);
        n4 = kC * kC / 4;
        split_kernel<<<(n4 + 255) / 256, 256>>>(Wproj, wpH, wpL, n4);
    }

    // 1) QKV projection -> head-major qkv
    dim3 g1(kQKV / 128, kM / 128);
    bf16x3_gemm_cp<OUT_QKV_HM><<<g1, 256, SMEM_GEMM>>>(
        xH, xL, wqH, wqL, nullptr, nullptr, kM, kQKV, kC);

    // 2) Channel-attention logits on tensor cores
    attn_logits_mma<<<dim3(kSplits, kB * kH), 256>>>();

    // 3) Softmax
    softmax_kernel<<<kB * kH * kD, kD>>>(alpha);

    // 4) P @ V^T on tensor cores (emits split bf16 out)
    pv_mma<<<dim3(kN / 64, kB * kH), 256>>>();

    // 5) Output projection + bias
    dim3 g3(kC / 128, kM / 128);
    bf16x3_gemm_cp<OUT_PLAIN_BIAS><<<g3, 256, SMEM_GEMM>>>(
        oH, oL, wpH, wpL, (float*)d_out, bproj, kM, kC, kC);
}